// round 9
// baseline (speedup 1.0000x reference)
#include <cuda_runtime.h>
#include <cuda_bf16.h>

// Problem constants
#define Bsz   64
#define Tsz   512
#define Kdim  1024     // IN_DIM
#define Hdim  1024     // HID
#define Mdim  (Bsz * Tsz)   // 32768 rows of the GEMM

// exp(-1/20); compiler rounds to nearest f32, same as XLA's f64->f32 constant
#define ALPHA_F 0.95122942450071400910f
#define THRESH_F 1.0f

// Eigen gebp K-panel size (computeProductBlockingSizes caps kc at 320)
#define KC 320

// 128 MB scratch for the pre-activation currents I[b,t,h]
__device__ float g_I[(size_t)Mdim * Hdim];

// ---------------------------------------------------------------------------
// GEMM: I[m,n] = sum_k x[m,k] * W[n,k] + bias[n]   ("NT", both K-contiguous)
//
// ROUNDING CONTRACT (Eigen gebp replication):
//   per output element:
//     c0 = fma-chain over k =   0..319   (natural order, acc starts at 0)
//     c1 = fma-chain over k = 320..639
//     c2 = fma-chain over k = 640..959
//     c3 = fma-chain over k = 960..1023
//     total = (((0 + c0) + c1) + c2) + c3     [plain fp32 adds, in order]
//     I     = total + bias                     [one add at the end]
//   (0 + c0 is exact, so the leading zero-init is harmless.)
//
// Tiling: 128x64 block tile, BK=8, 256 threads, 8x4 micro-tile.
// ---------------------------------------------------------------------------
#define BM 128
#define BN 64
#define BK 8
#define TM 8
#define TN 4
#define SPAD 4

__global__ __launch_bounds__(256, 2)
void snn_gemm_kernel(const float* __restrict__ A,      // [M, K] = x
                     const float* __restrict__ Bmat,   // [N, K] = W
                     const float* __restrict__ bias,   // [N]
                     float* __restrict__ C)            // [M, N] = I
{
    __shared__ float As[BK][BM + SPAD];
    __shared__ float Bs[BK][BN + SPAD];

    const int tid = threadIdx.x;
    const int bm  = blockIdx.y * BM;
    const int bn  = blockIdx.x * BN;

    const float* Ablk = A    + (size_t)bm * Kdim;
    const float* Bblk = Bmat + (size_t)bn * Kdim;

    // A load: 128 rows x 8 k = 1024 floats -> 256 threads x 1 float4.
    const int a_row = tid >> 1;           // 0..127
    const int a_col = (tid & 1) * 4;      // 0 or 4
    // B load: 64 rows x 8 k = 512 floats -> threads 0..127 x 1 float4.
    const int b_row = tid >> 1;           // rows 0..63 (tid < 128)
    const int b_col = (tid & 1) * 4;

    // Compute mapping: 16x16 thread grid; 8 rows x 4 cols per thread.
    const int tx = tid & 15;              // col group: 16 * 4 = 64 cols
    const int ty = tid >> 4;              // row group: 16 * 8 = 128 rows

    float acc[TM][TN];    // current K-panel chain
    float tot[TM][TN];    // running sum of completed panels
#pragma unroll
    for (int i = 0; i < TM; i++)
#pragma unroll
        for (int j = 0; j < TN; j++) { acc[i][j] = 0.0f; tot[i][j] = 0.0f; }

    for (int k0 = 0; k0 < Kdim; k0 += BK) {
        {
            float4 av = *(const float4*)(Ablk + (size_t)a_row * Kdim + k0 + a_col);
            As[a_col + 0][a_row] = av.x;
            As[a_col + 1][a_row] = av.y;
            As[a_col + 2][a_row] = av.z;
            As[a_col + 3][a_row] = av.w;
        }
        if (tid < 128) {
            float4 bv = *(const float4*)(Bblk + (size_t)b_row * Kdim + k0 + b_col);
            Bs[b_col + 0][b_row] = bv.x;
            Bs[b_col + 1][b_row] = bv.y;
            Bs[b_col + 2][b_row] = bv.z;
            Bs[b_col + 3][b_row] = bv.w;
        }
        __syncthreads();

#pragma unroll
        for (int k = 0; k < BK; k++) {
            float ar[TM], br[TN];
#pragma unroll
            for (int i = 0; i < TM; i++) ar[i] = As[k][ty * TM + i];
#pragma unroll
            for (int j = 0; j < TN; j++) br[j] = Bs[k][tx * TN + j];
#pragma unroll
            for (int i = 0; i < TM; i++)
#pragma unroll
                for (int j = 0; j < TN; j++)
                    acc[i][j] = fmaf(ar[i], br[j], acc[i][j]);
        }

        __syncthreads();

        // Fold at Eigen K-panel boundaries: k = 320, 640, 960, 1024.
        const int knext = k0 + BK;
        if (knext == KC || knext == 2 * KC || knext == 3 * KC || knext == Kdim) {
#pragma unroll
            for (int i = 0; i < TM; i++)
#pragma unroll
                for (int j = 0; j < TN; j++) {
                    tot[i][j] = __fadd_rn(tot[i][j], acc[i][j]);
                    acc[i][j] = 0.0f;
                }
        }
    }

    // Epilogue: add bias once at the end (matches reference's einsum + b).
    float bvals[TN];
#pragma unroll
    for (int j = 0; j < TN; j++) bvals[j] = bias[bn + tx * TN + j];

#pragma unroll
    for (int i = 0; i < TM; i++) {
        const int row = bm + ty * TM + i;
        float* crow = C + (size_t)row * Hdim + bn + tx * TN;
        float4 v;
        v.x = __fadd_rn(tot[i][0], bvals[0]);
        v.y = __fadd_rn(tot[i][1], bvals[1]);
        v.z = __fadd_rn(tot[i][2], bvals[2]);
        v.w = __fadd_rn(tot[i][3], bvals[3]);
        *(float4*)crow = v;
    }
}

// ---------------------------------------------------------------------------
// LIF scan: one thread per (b, h); h contiguous -> fully coalesced.
//
// ROUNDING CONTRACT (XLA:CPU — no FMA contraction in emitted LLVM IR):
//   m   = (alpha * mem) + I_t        [separate mul, add]
//   s   = m >= 1.0 ? 1 : 0
//   mem = m * (1.0 - s)              [separate sub, mul]
// Intrinsics used so ptxas cannot re-contract.
// ---------------------------------------------------------------------------
__global__ __launch_bounds__(256)
void snn_scan_kernel(const float* __restrict__ I,
                     float* __restrict__ spikes,     // [B, T, H]
                     float* __restrict__ mem_final)  // [B, H]
{
    const int gid = blockIdx.x * blockDim.x + threadIdx.x;  // 0 .. B*H-1
    const int b = gid >> 10;       // / Hdim
    const int h = gid & (Hdim - 1);

    const size_t base = ((size_t)b * Tsz) * Hdim + h;

    float mem = 0.0f;
#pragma unroll 4
    for (int t = 0; t < Tsz; t++) {
        const float cur = I[base + (size_t)t * Hdim];
        const float m = __fadd_rn(__fmul_rn(ALPHA_F, mem), cur);
        const float s = (m >= THRESH_F) ? 1.0f : 0.0f;
        spikes[base + (size_t)t * Hdim] = s;
        mem = __fmul_rn(m, __fsub_rn(1.0f, s));
    }
    mem_final[gid] = mem;
}

// ---------------------------------------------------------------------------
// Launch
// ---------------------------------------------------------------------------
extern "C" void kernel_launch(void* const* d_in, const int* in_sizes, int n_in,
                              void* d_out, int out_size)
{
    const float* x    = (const float*)d_in[0];   // [B, T, IN]
    const float* W    = (const float*)d_in[1];   // [H, IN]
    const float* bias = (const float*)d_in[2];   // [H]

    float* out        = (float*)d_out;
    float* spikes     = out;                                  // [B,T,H]
    float* mem_final  = out + (size_t)Mdim * Hdim;            // [B,H]

    float* I;
    cudaGetSymbolAddress((void**)&I, g_I);

    dim3 ggrid(Hdim / BN, Mdim / BM);   // (16, 256)
    snn_gemm_kernel<<<ggrid, 256>>>(x, W, bias, I);

    const int nseq = Bsz * Hdim;        // 65536
    snn_scan_kernel<<<nseq / 256, 256>>>(I, spikes, mem_final);
}

// round 11
// speedup vs baseline: 1.6376x; 1.6376x over previous
#include <cuda_runtime.h>
#include <cuda_bf16.h>

// Problem constants
#define Bsz   64
#define Tsz   512
#define Kdim  1024     // IN_DIM
#define Hdim  1024     // HID
#define Mdim  (Bsz * Tsz)   // 32768 rows of the GEMM

// exp(-1/20); compiler rounds to nearest f32, same as XLA's f64->f32 constant
#define ALPHA_F 0.95122942450071400910f
#define THRESH_F 1.0f

// Eigen gebp K-panel size (computeProductBlockingSizes caps kc at 320)
#define KC 320

// 128 MB scratch for the pre-activation currents I[b,t,h]
__device__ float g_I[(size_t)Mdim * Hdim];

// ---------------------------------------------------------------------------
// GEMM: I[m,n] = sum_k x[m,k] * W[n,k] + bias[n]   ("NT", both K-contiguous)
//
// ROUNDING CONTRACT (validated bit-exact in R9, rel_err 4e-7 -- DO NOT CHANGE):
//   per output element:
//     c0 = fma-chain over k =   0..319   (natural order, acc starts at 0)
//     c1 = fma-chain over k = 320..639
//     c2 = fma-chain over k = 640..959
//     c3 = fma-chain over k = 960..1023
//     total = (((0 + c0) + c1) + c2) + c3     [plain fp32 adds, in order]
//     I     = total + bias                     [one add at the end]
//
// Speed round: 128x128 block tile, 8x8 micro-tile (FFMA ~93% of issue mix),
// register-prefetch double-buffering to hide global-load latency.
// ---------------------------------------------------------------------------
#define BM 128
#define BN 128
#define BK 8
#define TM 8
#define TN 8
#define SPAD 4   // smem padding to kill store bank conflicts

__global__ __launch_bounds__(256, 1)
void snn_gemm_kernel(const float* __restrict__ A,      // [M, K] = x
                     const float* __restrict__ Bmat,   // [N, K] = W
                     const float* __restrict__ bias,   // [N]
                     float* __restrict__ C)            // [M, N] = I
{
    __shared__ float As[BK][BM + SPAD];
    __shared__ float Bs[BK][BN + SPAD];

    const int tid = threadIdx.x;
    const int bm  = blockIdx.y * BM;
    const int bn  = blockIdx.x * BN;

    const float* Ablk = A    + (size_t)bm * Kdim;
    const float* Bblk = Bmat + (size_t)bn * Kdim;

    // Load assignment: 2 threads per row, each loads one float4 of K.
    // A tile: 128 rows x 8 k;  B tile: 128 rows x 8 k. All 256 threads used.
    const int l_row = tid >> 1;           // 0..127
    const int l_col = (tid & 1) * 4;      // 0 or 4

    // Compute mapping: 16x16 thread grid; 8 rows x 8 cols per thread.
    const int tx = tid & 15;              // col group: 16 * 8 = 128 cols
    const int ty = tid >> 4;              // row group: 16 * 8 = 128 rows

    float acc[TM][TN];    // current K-panel chain
    float tot[TM][TN];    // running sum of completed panels
#pragma unroll
    for (int i = 0; i < TM; i++)
#pragma unroll
        for (int j = 0; j < TN; j++) { acc[i][j] = 0.0f; tot[i][j] = 0.0f; }

    // Prefetch tile 0 into registers.
    const float* aptr = Ablk + (size_t)l_row * Kdim + l_col;
    const float* bptr = Bblk + (size_t)l_row * Kdim + l_col;
    float4 av = *(const float4*)(aptr);
    float4 bv = *(const float4*)(bptr);

    for (int k0 = 0; k0 < Kdim; k0 += BK) {
        // Commit prefetched tile to shared memory (transposed: smem[k][row]).
        As[l_col + 0][l_row] = av.x;
        As[l_col + 1][l_row] = av.y;
        As[l_col + 2][l_row] = av.z;
        As[l_col + 3][l_row] = av.w;
        Bs[l_col + 0][l_row] = bv.x;
        Bs[l_col + 1][l_row] = bv.y;
        Bs[l_col + 2][l_row] = bv.z;
        Bs[l_col + 3][l_row] = bv.w;
        __syncthreads();

        // Prefetch next tile (latency overlaps the compute below).
        if (k0 + BK < Kdim) {
            av = *(const float4*)(aptr + k0 + BK);
            bv = *(const float4*)(bptr + k0 + BK);
        }

#pragma unroll
        for (int k = 0; k < BK; k++) {
            float ar[TM], br[TN];
#pragma unroll
            for (int i = 0; i < TM; i++) ar[i] = As[k][ty * TM + i];
#pragma unroll
            for (int j = 0; j < TN; j++) br[j] = Bs[k][tx * TN + j];
#pragma unroll
            for (int i = 0; i < TM; i++)
#pragma unroll
                for (int j = 0; j < TN; j++)
                    acc[i][j] = fmaf(ar[i], br[j], acc[i][j]);
        }

        // Fold at Eigen K-panel boundaries: k = 320, 640, 960, 1024.
        const int knext = k0 + BK;
        if (knext == KC || knext == 2 * KC || knext == 3 * KC || knext == Kdim) {
#pragma unroll
            for (int i = 0; i < TM; i++)
#pragma unroll
                for (int j = 0; j < TN; j++) {
                    tot[i][j] = __fadd_rn(tot[i][j], acc[i][j]);
                    acc[i][j] = 0.0f;
                }
        }

        __syncthreads();   // guard smem overwrite by next iteration's stores
    }

    // Epilogue: add bias once at the end (matches reference's einsum + b).
    float bvals[TN];
#pragma unroll
    for (int j = 0; j < TN; j++) bvals[j] = bias[bn + tx * TN + j];

#pragma unroll
    for (int i = 0; i < TM; i++) {
        const int row = bm + ty * TM + i;
        float* crow = C + (size_t)row * Hdim + bn + tx * TN;
#pragma unroll
        for (int j = 0; j < TN; j += 4) {
            float4 v;
            v.x = __fadd_rn(tot[i][j + 0], bvals[j + 0]);
            v.y = __fadd_rn(tot[i][j + 1], bvals[j + 1]);
            v.z = __fadd_rn(tot[i][j + 2], bvals[j + 2]);
            v.w = __fadd_rn(tot[i][j + 3], bvals[j + 3]);
            *(float4*)(crow + j) = v;
        }
    }
}

// ---------------------------------------------------------------------------
// LIF scan. ROUNDING CONTRACT (validated): separate mul/add/sub per element:
//   m   = (alpha * mem) + I_t
//   s   = m >= 1.0 ? 1 : 0
//   mem = m * (1.0 - s)
// Speed round: float2 lanes (each thread owns 2 adjacent h), unroll 8 so
// eight independent 8B loads are in flight per thread (~2 MB chip-wide ->
// approaches the LTS/HBM throughput cap instead of being latency-bound).
// ---------------------------------------------------------------------------
#define SCAN_TPB 128

__global__ __launch_bounds__(SCAN_TPB)
void snn_scan_kernel(const float2* __restrict__ I2,
                     float2* __restrict__ spikes2,     // [B, T, H/2]
                     float2* __restrict__ memf2)       // [B, H/2]
{
    const int gid = blockIdx.x * SCAN_TPB + threadIdx.x;  // 0 .. B*H/2-1
    const int H2  = Hdim / 2;                              // 512
    const int b   = gid >> 9;        // / H2
    const int h2  = gid & (H2 - 1);

    const size_t base = ((size_t)b * Tsz) * H2 + h2;

    float mx = 0.0f, my = 0.0f;
#pragma unroll 8
    for (int t = 0; t < Tsz; t++) {
        const float2 cur = I2[base + (size_t)t * H2];

        const float ax = __fadd_rn(__fmul_rn(ALPHA_F, mx), cur.x);
        const float ay = __fadd_rn(__fmul_rn(ALPHA_F, my), cur.y);
        const float sx = (ax >= THRESH_F) ? 1.0f : 0.0f;
        const float sy = (ay >= THRESH_F) ? 1.0f : 0.0f;

        float2 sp; sp.x = sx; sp.y = sy;
        spikes2[base + (size_t)t * H2] = sp;

        mx = __fmul_rn(ax, __fsub_rn(1.0f, sx));
        my = __fmul_rn(ay, __fsub_rn(1.0f, sy));
    }
    float2 mf; mf.x = mx; mf.y = my;
    memf2[gid] = mf;
}

// ---------------------------------------------------------------------------
// Launch
// ---------------------------------------------------------------------------
extern "C" void kernel_launch(void* const* d_in, const int* in_sizes, int n_in,
                              void* d_out, int out_size)
{
    const float* x    = (const float*)d_in[0];   // [B, T, IN]
    const float* W    = (const float*)d_in[1];   // [H, IN]
    const float* bias = (const float*)d_in[2];   // [H]

    float* out        = (float*)d_out;
    float* spikes     = out;                                  // [B,T,H]
    float* mem_final  = out + (size_t)Mdim * Hdim;            // [B,H]

    float* I;
    cudaGetSymbolAddress((void**)&I, g_I);

    dim3 ggrid(Hdim / BN, Mdim / BM);   // (8, 256)
    snn_gemm_kernel<<<ggrid, 256>>>(x, W, bias, I);

    const int nlanes = Bsz * Hdim / 2;  // 32768 float2 lanes
    snn_scan_kernel<<<nlanes / SCAN_TPB, SCAN_TPB>>>(
        (const float2*)I, (float2*)spikes, (float2*)mem_final);
}